// round 13
// baseline (speedup 1.0000x reference)
#include <cuda_runtime.h>
#include <math.h>

// TimeLSTMHyp: B=64, S=128, H=I=512
//  1) Precompute mobius_matvec(U_g, x) for all (b,s,g): big FFMA2 GEMM + scaling pass (also stores ||mu_g||).
//  2) 128 captured steps:
//       gemm_step: z = [h|c] @ Wbig^T via packed f32x2 FFMA2, BM=64/BN=128, split-K=16
//       elem_step: Poincare-ball math, 8 reduction rounds (analytic scalar norms), sums split-K partials.

#define MIN_NORM 1e-15f
#define KSLICES 16

// ---------------- static device scratch ----------------
__device__ float g_mu[8192u * 2048u];        // mobius_matvec(U_g, x): [b*128+s][g*512+j] (64 MB)
__device__ float g_tmu[8192u * 4u];          // per-row per-gate ||mu_g|| = tanh(ng/xn*artanh(xn))
__device__ float g_wbig[2560 * 512];         // rows 0..2047: gate-major W_all; 2048..2559: W_d
__device__ float g_z[KSLICES * 64 * 2560];   // split-K partials per step
__device__ float g_h[64 * 512];
__device__ float g_c[64 * 512];

// ---------------- helpers ----------------
__device__ __forceinline__ float artanhc(float x) {
    x = fminf(fmaxf(x, -1.0f + 1e-5f), 1.0f - 1e-5f);
    return atanhf(x);
}
__device__ __forceinline__ float clampn(float sumsq) {
    return fmaxf(sqrtf(sumsq), MIN_NORM);
}
__device__ __forceinline__ float sigm(float x) { return 1.0f / (1.0f + expf(-x)); }

// packed f32x2 (FFMA2) helpers
__device__ __forceinline__ unsigned long long dup_f32(float x) {
    unsigned long long r;
    asm("mov.b64 %0, {%1, %1};" : "=l"(r) : "f"(x));
    return r;
}
__device__ __forceinline__ void fma_x2(unsigned long long& d, unsigned long long a, unsigned long long b) {
    asm("fma.rn.f32x2 %0, %1, %2, %0;" : "+l"(d) : "l"(a), "l"(b));
}
__device__ __forceinline__ float2 unpack_x2(unsigned long long v) {
    float2 r;
    asm("mov.b64 {%0, %1}, %2;" : "=f"(r.x), "=f"(r.y) : "l"(v));
    return r;
}

template <int N>
__device__ __forceinline__ void block_reduce_sum(float* v) {
    __shared__ float sh[N][17];
    const int lane = threadIdx.x & 31;
    const int wid  = threadIdx.x >> 5;
    #pragma unroll
    for (int i = 0; i < N; i++) {
        float x = v[i];
        #pragma unroll
        for (int o = 16; o > 0; o >>= 1) x += __shfl_xor_sync(0xffffffffu, x, o);
        if (lane == 0) sh[i][wid] = x;
    }
    __syncthreads();
    if (wid == 0) {
        const int nw = blockDim.x >> 5;
        #pragma unroll
        for (int i = 0; i < N; i++) {
            float x = (lane < nw) ? sh[i][lane] : 0.0f;
            #pragma unroll
            for (int o = 8; o > 0; o >>= 1) x += __shfl_xor_sync(0xffffffffu, x, o);
            if (lane == 0) sh[i][16] = x;
        }
    }
    __syncthreads();
    #pragma unroll
    for (int i = 0; i < N; i++) v[i] = sh[i][16];
    __syncthreads();
}

// ---------------- weight rearrangement ----------------
__global__ void prep_w(const float* __restrict__ Wall, const float* __restrict__ Wd) {
    int idx = blockIdx.x * blockDim.x + threadIdx.x;
    if (idx >= 2560 * 512) return;
    int m = idx >> 9, k = idx & 511;
    float v;
    if (m < 2048) {
        int g = m >> 9, jj = m & 511;
        v = Wall[jj * 2048 + (g << 9) + k];
    } else {
        v = Wd[(m - 2048) * 512 + k];
    }
    g_wbig[idx] = v;
}

// ---------------- precompute GEMM: g_mu[r][m] = sum_k X[r,k]*U_all[m,k] ----------------
__global__ void __launch_bounds__(256) gemm_pre(const float* __restrict__ A, const float* __restrict__ U) {
    __shared__ float As[16][132];
    __shared__ float Bs[16][132];
    const int bx = blockIdx.x;
    const int by = blockIdx.y;
    const int tid = threadIdx.x;
    const int lr  = tid >> 1;
    const int lc8 = (tid & 1) << 3;
    const float* Ar = A + (size_t)(by * 128 + lr) * 512 + lc8;
    const float* Ur = U + (size_t)(bx * 128 + lr) * 512 + lc8;
    const int ty = tid >> 4, tx = tid & 15;

    unsigned long long acc[4][8];
    #pragma unroll
    for (int i = 0; i < 4; i++)
        #pragma unroll
        for (int j = 0; j < 8; j++) acc[i][j] = 0ull;

    for (int k0 = 0; k0 < 512; k0 += 16) {
        float4 a0 = *(const float4*)(Ar + k0);
        float4 a1 = *(const float4*)(Ar + k0 + 4);
        float4 b0 = *(const float4*)(Ur + k0);
        float4 b1 = *(const float4*)(Ur + k0 + 4);
        __syncthreads();
        As[lc8 + 0][lr] = a0.x; As[lc8 + 1][lr] = a0.y; As[lc8 + 2][lr] = a0.z; As[lc8 + 3][lr] = a0.w;
        As[lc8 + 4][lr] = a1.x; As[lc8 + 5][lr] = a1.y; As[lc8 + 6][lr] = a1.z; As[lc8 + 7][lr] = a1.w;
        Bs[lc8 + 0][lr] = b0.x; Bs[lc8 + 1][lr] = b0.y; Bs[lc8 + 2][lr] = b0.z; Bs[lc8 + 3][lr] = b0.w;
        Bs[lc8 + 4][lr] = b1.x; Bs[lc8 + 5][lr] = b1.y; Bs[lc8 + 6][lr] = b1.z; Bs[lc8 + 7][lr] = b1.w;
        __syncthreads();
        #pragma unroll
        for (int kk = 0; kk < 16; kk++) {
            ulonglong2 apA = *(const ulonglong2*)&As[kk][ty * 8];
            ulonglong2 apB = *(const ulonglong2*)&As[kk][ty * 8 + 4];
            #pragma unroll
            for (int j = 0; j < 8; j++) {
                unsigned long long bd = dup_f32(Bs[kk][tx + 16 * j]);
                fma_x2(acc[0][j], apA.x, bd);
                fma_x2(acc[1][j], apA.y, bd);
                fma_x2(acc[2][j], apB.x, bd);
                fma_x2(acc[3][j], apB.y, bd);
            }
        }
    }
    float* C = g_mu + (size_t)(by * 128 + ty * 8) * 2048 + bx * 128 + tx;
    #pragma unroll
    for (int ip = 0; ip < 4; ip++) {
        #pragma unroll
        for (int j = 0; j < 8; j++) {
            float2 v = unpack_x2(acc[ip][j]);
            C[(size_t)(2 * ip + 0) * 2048 + j * 16] = v.x;
            C[(size_t)(2 * ip + 1) * 2048 + j * 16] = v.y;
        }
    }
}

// ---------------- scale precomputed mu + store analytic norms ----------------
__global__ void scale_mu(const float* __restrict__ X) {
    const int r = blockIdx.x;
    const int j = threadIdx.x;
    float xj = X[(size_t)r * 512 + j];
    float* mrow = g_mu + (size_t)r * 2048;
    float m0 = mrow[j], m1 = mrow[512 + j], m2 = mrow[1024 + j], m3 = mrow[1536 + j];
    float v[5] = {xj * xj, m0 * m0, m1 * m1, m2 * m2, m3 * m3};
    block_reduce_sum<5>(v);
    float xn = clampn(v[0]);
    float at = artanhc(xn);
    float n0 = clampn(v[1]); float t0 = tanhf(n0 / xn * at); mrow[j]        = t0 / n0 * m0;
    float n1 = clampn(v[2]); float t1 = tanhf(n1 / xn * at); mrow[512 + j]  = t1 / n1 * m1;
    float n2 = clampn(v[3]); float t2 = tanhf(n2 / xn * at); mrow[1024 + j] = t2 / n2 * m2;
    float n3 = clampn(v[4]); float t3 = tanhf(n3 / xn * at); mrow[1536 + j] = t3 / n3 * m3;
    if (j == 0) {
        g_tmu[r * 4 + 0] = t0; g_tmu[r * 4 + 1] = t1;
        g_tmu[r * 4 + 2] = t2; g_tmu[r * 4 + 3] = t3;
    }
}

// ---------------- per-step GEMM: z = [h|c] @ Wbig^T, FFMA2, split-K=16 ----------------
// grid (20, 16): BN=128 col-tile x 32-wide K-chunk. 128 threads, BM=64, 8x8 micro via f32x2.
__global__ void __launch_bounds__(128) gemm_step() {
    __shared__ float As[16][68];    // [kk][row 0..63]
    __shared__ float Bs[16][132];   // [kk][col 0..127]
    const int ct  = blockIdx.x;     // 0..19
    const int kc  = blockIdx.y;     // 0..15
    const int tid = threadIdx.x;
    const int col0 = ct * 128;
    const float* Ab = (ct < 16) ? g_h : g_c;
    const float* Bb = g_wbig + (size_t)col0 * 512;
    const int ty = tid >> 4;        // 0..7  -> rows 8ty..8ty+7
    const int tx = tid & 15;        // 0..15 -> cols 8tx..8tx+7
    const int alr  = tid >> 1;      // 0..63 (A fill row)
    const int alc8 = (tid & 1) << 3;
    const int kb = kc * 32;

    unsigned long long acc[8][4];
    #pragma unroll
    for (int r = 0; r < 8; r++)
        #pragma unroll
        for (int p = 0; p < 4; p++) acc[r][p] = 0ull;

    #pragma unroll
    for (int it = 0; it < 2; it++) {
        const int k0 = kb + it * 16;
        // A tile 64x16: 2 float4 per thread
        float4 a0 = *(const float4*)(Ab + (size_t)alr * 512 + k0 + alc8);
        float4 a1 = *(const float4*)(Ab + (size_t)alr * 512 + k0 + alc8 + 4);
        // B tile 128x16: 4 float4 per thread (row = tid)
        float4 b0 = *(const float4*)(Bb + (size_t)tid * 512 + k0 + 0);
        float4 b1 = *(const float4*)(Bb + (size_t)tid * 512 + k0 + 4);
        float4 b2 = *(const float4*)(Bb + (size_t)tid * 512 + k0 + 8);
        float4 b3 = *(const float4*)(Bb + (size_t)tid * 512 + k0 + 12);
        __syncthreads();
        As[alc8 + 0][alr] = a0.x; As[alc8 + 1][alr] = a0.y; As[alc8 + 2][alr] = a0.z; As[alc8 + 3][alr] = a0.w;
        As[alc8 + 4][alr] = a1.x; As[alc8 + 5][alr] = a1.y; As[alc8 + 6][alr] = a1.z; As[alc8 + 7][alr] = a1.w;
        Bs[ 0][tid] = b0.x; Bs[ 1][tid] = b0.y; Bs[ 2][tid] = b0.z; Bs[ 3][tid] = b0.w;
        Bs[ 4][tid] = b1.x; Bs[ 5][tid] = b1.y; Bs[ 6][tid] = b1.z; Bs[ 7][tid] = b1.w;
        Bs[ 8][tid] = b2.x; Bs[ 9][tid] = b2.y; Bs[10][tid] = b2.z; Bs[11][tid] = b2.w;
        Bs[12][tid] = b3.x; Bs[13][tid] = b3.y; Bs[14][tid] = b3.z; Bs[15][tid] = b3.w;
        __syncthreads();
        #pragma unroll
        for (int kk = 0; kk < 16; kk++) {
            ulonglong2 bp01 = *(const ulonglong2*)&Bs[kk][8 * tx];      // cols 8tx..8tx+3 (2 pairs)
            ulonglong2 bp23 = *(const ulonglong2*)&Bs[kk][8 * tx + 4];  // cols 8tx+4..8tx+7
            #pragma unroll
            for (int r = 0; r < 8; r++) {
                unsigned long long ad = dup_f32(As[kk][8 * ty + r]);    // broadcast load
                fma_x2(acc[r][0], ad, bp01.x);
                fma_x2(acc[r][1], ad, bp01.y);
                fma_x2(acc[r][2], ad, bp23.x);
                fma_x2(acc[r][3], ad, bp23.y);
            }
        }
    }
    float* Z = g_z + (size_t)kc * 64 * 2560;
    #pragma unroll
    for (int r = 0; r < 8; r++) {
        #pragma unroll
        for (int p = 0; p < 4; p++) {
            float2 v = unpack_x2(acc[r][p]);
            *(float2*)&Z[(size_t)(8 * ty + r) * 2560 + col0 + 8 * tx + 2 * p] = v;
        }
    }
}

// ---------------- per-step elementwise: 8 reduction rounds ----------------
__global__ void __launch_bounds__(512) elem_step(int step, const float* __restrict__ ts, float* __restrict__ out) {
    const int b = blockIdx.x;
    const int j = threadIdx.x;
    const float t = ts[b * 128 + step];
    const float cj = g_c[b * 512 + j];
    const float hj = g_h[b * 512 + j];

    float zg[4] = {0.f, 0.f, 0.f, 0.f};
    float mcd = 0.f;
    #pragma unroll
    for (int s = 0; s < KSLICES; s++) {
        const float* zp = g_z + (size_t)s * 64 * 2560 + (size_t)b * 2560;
        #pragma unroll
        for (int g = 0; g < 4; g++) zg[g] += zp[g * 512 + j];
        mcd += zp[2048 + j];
    }
    const size_t row = (size_t)b * 128 + step;
    const float* mup = g_mu + row * 2048;
    float mug[4], tmu[4];
    #pragma unroll
    for (int g = 0; g < 4; g++) { mug[g] = mup[g * 512 + j]; tmu[g] = g_tmu[row * 4 + g]; }

    // R1: ||c||^2, ||h||^2, ||mcd||^2, ||z_g||^2 x4, <z_g,mu_g> x4  (11)
    float r1[11] = {cj * cj, hj * hj, mcd * mcd,
                    zg[0] * zg[0], zg[1] * zg[1], zg[2] * zg[2], zg[3] * zg[3],
                    zg[0] * mug[0], zg[1] * mug[1], zg[2] * mug[2], zg[3] * mug[3]};
    block_reduce_sum<11>(r1);
    const float c2 = r1[0];
    const float cn = clampn(c2), hn = clampn(r1[1]), mcdn = clampn(r1[2]);
    const float athn = artanhc(hn);
    const float alpha = tanhf(mcdn / cn * artanhc(cn)) / mcdn;   // M1 = alpha*mcd
    const float M1n = fmaxf(fabsf(alpha) * mcdn, MIN_NORM);      // analytic ||M1||
    const float gamma = artanhc(M1n) / M1n * alpha;              // T = tanh(gamma*mcd)
    const float T = tanhf(gamma * mcd);
    float sg[4];
    #pragma unroll
    for (int g = 0; g < 4; g++) {   // s_g = mobius_add(Wp_g, mu_g), Wp_g = (tgh/zn)*z_g
        float zn = clampn(r1[3 + g]);
        float tgh = tanhf(zn / hn * athn);
        float wc = tgh / zn;
        float x2 = tgh * tgh;
        float y2 = tmu[g] * tmu[g];
        float xy = wc * r1[7 + g];
        float den = fmaxf(1.f + 2.f * xy + x2 * y2, MIN_NORM);
        sg[g] = ((1.f + 2.f * xy + y2) * wc * zg[g] + (1.f - x2) * mug[g]) / den;
    }

    // R2: ||T||^2, ||s_g||^2 x4  (5)
    float r2[5] = {T * T, sg[0] * sg[0], sg[1] * sg[1], sg[2] * sg[2], sg[3] * sg[3]};
    block_reduce_sum<5>(r2);
    const float Tn = clampn(r2[0]);
    const float cs1n = tanhf(Tn);              // analytic ||c_s1||
    const float cs1 = cs1n / Tn * T;
    const float cs1_2 = cs1n * cs1n;
    float gate[4];
    #pragma unroll
    for (int g = 0; g < 4; g++) {
        float sn = clampn(r2[1 + g]);
        gate[g] = sigm(artanhc(sn) / sn * sg[g]);
    }
    const float gf = gate[0], gi = gate[1], go = gate[2], ctm = gate[3];
    out[row * 512 + j] = go;

    // R3: <cs1,c>, ||c_tmp||^2, ||i*c_tmp||^2  (3)
    const float ict = gi * ctm;
    float r3[3] = {cs1 * cj, ctm * ctm, ict * ict};
    block_reduce_sum<3>(r3);
    const float xy1 = -r3[0];
    // c_s2 = pw_mul(c_s1, t): analytic-norm scalar chain
    const float ta = fabsf(t);
    const float xn_t  = fmaxf(ta * 22.62741699796952f /*sqrt(512)*/, MIN_NORM);
    const float wxn_t = fmaxf(ta * cs1n, MIN_NORM);
    const float cs2n = tanhf(wxn_t / xn_t * artanhc(xn_t));
    const float cs2 = cs2n / wxn_t * t * cs1;
    const float cs2sq = cs2n * cs2n;
    // c_l = mobius_add(-c_s1, c)
    const float denl = fmaxf(1.f + 2.f * xy1 + cs1_2 * c2, MIN_NORM);
    const float cl = ((1.f + 2.f * xy1 + c2) * (-cs1) + (1.f - cs1_2) * cj) / denl;
    // P = pw_mul(i, c_tmp)
    const float ctn = clampn(r3[1]), ictn = clampn(r3[2]);
    const float Pn = tanhf(ictn / ctn * artanhc(ctn));
    const float P = Pn / ictn * ict;
    const float P2s = Pn * Pn;

    // R4: ||cl||^2, <cl,cs2>  (2)
    float r4[2] = {cl * cl, cl * cs2};
    block_reduce_sum<2>(r4);
    const float cln2 = r4[0], xy5 = r4[1];
    const float den5 = fmaxf(1.f + 2.f * xy5 + cln2 * cs2sq, MIN_NORM);
    const float cadj = ((1.f + 2.f * xy5 + cs2sq) * cl + (1.f - cln2) * cs2) / den5;

    // R5: ||cadj||^2, ||f*cadj||^2  (2)
    const float fca = gf * cadj;
    float r5[2] = {cadj * cadj, fca * fca};
    block_reduce_sum<2>(r5);
    const float cadjn = clampn(r5[0]), fcan = clampn(r5[1]);
    const float Qn = tanhf(fcan / cadjn * artanhc(cadjn));
    const float Q = Qn / fcan * fca;
    const float Q2 = Qn * Qn;

    // R6: <P,Q>  (1)
    float r6[1] = {P * Q};
    block_reduce_sum<1>(r6);
    const float den7 = fmaxf(1.f + 2.f * r6[0] + P2s * Q2, MIN_NORM);
    const float cnew = ((1.f + 2.f * r6[0] + Q2) * P + (1.f - P2s) * Q) / den7;

    // R7: ||u||^2, u = tanh(cnew)  (1)
    const float u = tanhf(cnew);
    float r7[1] = {u * u};
    block_reduce_sum<1>(r7);
    const float un = clampn(r7[0]);
    const float en_exact = tanhf(un);
    const float e = en_exact / un * u;
    const float en = fmaxf(en_exact, MIN_NORM);

    // R8: ||o*e||^2  (1)
    const float oe = go * e;
    float r8[1] = {oe * oe};
    block_reduce_sum<1>(r8);
    const float oen = clampn(r8[0]);
    const float hnew = tanhf(oen / en * artanhc(en)) / oen * oe;

    g_h[b * 512 + j] = hnew;
    g_c[b * 512 + j] = cnew;
    if (step == 127) {
        out[(size_t)64 * 128 * 512 + (size_t)b * 512 + j] = hnew;
        out[(size_t)64 * 128 * 512 + (size_t)64 * 512 + (size_t)b * 512 + j] = cnew;
    }
}

// ---------------- launch ----------------
extern "C" void kernel_launch(void* const* d_in, const int* in_sizes, int n_in,
                              void* d_out, int out_size) {
    const float* inputs = (const float*)d_in[0];
    const float* ts     = (const float*)d_in[1];
    const float* h0     = (const float*)d_in[2];
    const float* c0     = (const float*)d_in[3];
    const float* Wall   = (const float*)d_in[4];
    const float* Uall   = (const float*)d_in[5];
    const float* Wd     = (const float*)d_in[6];
    float* out = (float*)d_out;

    cudaMemcpyToSymbolAsync(g_h, h0, 64 * 512 * sizeof(float), 0, cudaMemcpyDeviceToDevice, 0);
    cudaMemcpyToSymbolAsync(g_c, c0, 64 * 512 * sizeof(float), 0, cudaMemcpyDeviceToDevice, 0);

    prep_w<<<(2560 * 512 + 255) / 256, 256>>>(Wall, Wd);
    gemm_pre<<<dim3(16, 64), 256>>>(inputs, Uall);
    scale_mu<<<8192, 512>>>(inputs);

    for (int t = 0; t < 128; t++) {
        gemm_step<<<dim3(20, 16), 128>>>();
        elem_step<<<64, 512>>>(t, ts, out);
    }
}

// round 14
// speedup vs baseline: 1.4851x; 1.4851x over previous
#include <cuda_runtime.h>
#include <math.h>
#include <stdint.h>

// TimeLSTMHyp: B=64, S=128, H=I=512
//  1) Precompute mobius_matvec(U_g, x) for all (b,s,g): FFMA2 GEMM (exact fp32) + scaling pass.
//  2) 128 captured steps:
//       gemm_step: z = [h|c] @ Wbig^T via mma.sync tf32 tensor cores, split-K=8
//       elem_step: Poincare-ball math, 8 reduction rounds (analytic scalar norms), sums split-K partials.

#define MIN_NORM 1e-15f
#define KSLICES 8

// ---------------- static device scratch ----------------
__device__ float g_mu[8192u * 2048u];        // mobius_matvec(U_g, x): [b*128+s][g*512+j] (64 MB)
__device__ float g_tmu[8192u * 4u];          // per-row per-gate ||mu_g||
__device__ float g_wbig[2560 * 512];         // tf32-rounded: rows 0..2047 gate-major W_all; 2048..2559 W_d
__device__ float g_z[KSLICES * 64 * 2560];   // split-K partials per step
__device__ float g_h[64 * 512];
__device__ float g_c[64 * 512];

// ---------------- helpers ----------------
__device__ __forceinline__ float artanhc(float x) {
    x = fminf(fmaxf(x, -1.0f + 1e-5f), 1.0f - 1e-5f);
    return atanhf(x);
}
__device__ __forceinline__ float clampn(float sumsq) {
    return fmaxf(sqrtf(sumsq), MIN_NORM);
}
__device__ __forceinline__ float sigm(float x) { return 1.0f / (1.0f + expf(-x)); }

__device__ __forceinline__ float cvt_tf32(float x) {
    uint32_t r;
    asm("cvt.rna.tf32.f32 %0, %1;" : "=r"(r) : "f"(x));
    return __uint_as_float(r);
}

// packed f32x2 (FFMA2) helpers — used in exact-fp32 precompute GEMM
__device__ __forceinline__ unsigned long long dup_f32(float x) {
    unsigned long long r;
    asm("mov.b64 %0, {%1, %1};" : "=l"(r) : "f"(x));
    return r;
}
__device__ __forceinline__ void fma_x2(unsigned long long& d, unsigned long long a, unsigned long long b) {
    asm("fma.rn.f32x2 %0, %1, %2, %0;" : "+l"(d) : "l"(a), "l"(b));
}
__device__ __forceinline__ float2 unpack_x2(unsigned long long v) {
    float2 r;
    asm("mov.b64 {%0, %1}, %2;" : "=f"(r.x), "=f"(r.y) : "l"(v));
    return r;
}

template <int N>
__device__ __forceinline__ void block_reduce_sum(float* v) {
    __shared__ float sh[N][17];
    const int lane = threadIdx.x & 31;
    const int wid  = threadIdx.x >> 5;
    #pragma unroll
    for (int i = 0; i < N; i++) {
        float x = v[i];
        #pragma unroll
        for (int o = 16; o > 0; o >>= 1) x += __shfl_xor_sync(0xffffffffu, x, o);
        if (lane == 0) sh[i][wid] = x;
    }
    __syncthreads();
    if (wid == 0) {
        const int nw = blockDim.x >> 5;
        #pragma unroll
        for (int i = 0; i < N; i++) {
            float x = (lane < nw) ? sh[i][lane] : 0.0f;
            #pragma unroll
            for (int o = 8; o > 0; o >>= 1) x += __shfl_xor_sync(0xffffffffu, x, o);
            if (lane == 0) sh[i][16] = x;
        }
    }
    __syncthreads();
    #pragma unroll
    for (int i = 0; i < N; i++) v[i] = sh[i][16];
    __syncthreads();
}

// ---------------- weight rearrangement (+ tf32 rounding for the mma path) ----------------
__global__ void prep_w(const float* __restrict__ Wall, const float* __restrict__ Wd) {
    int idx = blockIdx.x * blockDim.x + threadIdx.x;
    if (idx >= 2560 * 512) return;
    int m = idx >> 9, k = idx & 511;
    float v;
    if (m < 2048) {
        int g = m >> 9, jj = m & 511;
        v = Wall[jj * 2048 + (g << 9) + k];
    } else {
        v = Wd[(m - 2048) * 512 + k];
    }
    g_wbig[idx] = cvt_tf32(v);
}

// ---------------- precompute GEMM (exact fp32, FFMA2): g_mu[r][m] = sum_k X[r,k]*U_all[m,k] ----------------
__global__ void __launch_bounds__(256) gemm_pre(const float* __restrict__ A, const float* __restrict__ U) {
    __shared__ float As[16][132];
    __shared__ float Bs[16][132];
    const int bx = blockIdx.x;
    const int by = blockIdx.y;
    const int tid = threadIdx.x;
    const int lr  = tid >> 1;
    const int lc8 = (tid & 1) << 3;
    const float* Ar = A + (size_t)(by * 128 + lr) * 512 + lc8;
    const float* Ur = U + (size_t)(bx * 128 + lr) * 512 + lc8;
    const int ty = tid >> 4, tx = tid & 15;

    unsigned long long acc[4][8];
    #pragma unroll
    for (int i = 0; i < 4; i++)
        #pragma unroll
        for (int j = 0; j < 8; j++) acc[i][j] = 0ull;

    for (int k0 = 0; k0 < 512; k0 += 16) {
        float4 a0 = *(const float4*)(Ar + k0);
        float4 a1 = *(const float4*)(Ar + k0 + 4);
        float4 b0 = *(const float4*)(Ur + k0);
        float4 b1 = *(const float4*)(Ur + k0 + 4);
        __syncthreads();
        As[lc8 + 0][lr] = a0.x; As[lc8 + 1][lr] = a0.y; As[lc8 + 2][lr] = a0.z; As[lc8 + 3][lr] = a0.w;
        As[lc8 + 4][lr] = a1.x; As[lc8 + 5][lr] = a1.y; As[lc8 + 6][lr] = a1.z; As[lc8 + 7][lr] = a1.w;
        Bs[lc8 + 0][lr] = b0.x; Bs[lc8 + 1][lr] = b0.y; Bs[lc8 + 2][lr] = b0.z; Bs[lc8 + 3][lr] = b0.w;
        Bs[lc8 + 4][lr] = b1.x; Bs[lc8 + 5][lr] = b1.y; Bs[lc8 + 6][lr] = b1.z; Bs[lc8 + 7][lr] = b1.w;
        __syncthreads();
        #pragma unroll
        for (int kk = 0; kk < 16; kk++) {
            ulonglong2 apA = *(const ulonglong2*)&As[kk][ty * 8];
            ulonglong2 apB = *(const ulonglong2*)&As[kk][ty * 8 + 4];
            #pragma unroll
            for (int j = 0; j < 8; j++) {
                unsigned long long bd = dup_f32(Bs[kk][tx + 16 * j]);
                fma_x2(acc[0][j], apA.x, bd);
                fma_x2(acc[1][j], apA.y, bd);
                fma_x2(acc[2][j], apB.x, bd);
                fma_x2(acc[3][j], apB.y, bd);
            }
        }
    }
    float* C = g_mu + (size_t)(by * 128 + ty * 8) * 2048 + bx * 128 + tx;
    #pragma unroll
    for (int ip = 0; ip < 4; ip++) {
        #pragma unroll
        for (int j = 0; j < 8; j++) {
            float2 v = unpack_x2(acc[ip][j]);
            C[(size_t)(2 * ip + 0) * 2048 + j * 16] = v.x;
            C[(size_t)(2 * ip + 1) * 2048 + j * 16] = v.y;
        }
    }
}

// ---------------- scale precomputed mu + store analytic norms ----------------
__global__ void scale_mu(const float* __restrict__ X) {
    const int r = blockIdx.x;
    const int j = threadIdx.x;
    float xj = X[(size_t)r * 512 + j];
    float* mrow = g_mu + (size_t)r * 2048;
    float m0 = mrow[j], m1 = mrow[512 + j], m2 = mrow[1024 + j], m3 = mrow[1536 + j];
    float v[5] = {xj * xj, m0 * m0, m1 * m1, m2 * m2, m3 * m3};
    block_reduce_sum<5>(v);
    float xn = clampn(v[0]);
    float at = artanhc(xn);
    float n0 = clampn(v[1]); float t0 = tanhf(n0 / xn * at); mrow[j]        = t0 / n0 * m0;
    float n1 = clampn(v[2]); float t1 = tanhf(n1 / xn * at); mrow[512 + j]  = t1 / n1 * m1;
    float n2 = clampn(v[3]); float t2 = tanhf(n2 / xn * at); mrow[1024 + j] = t2 / n2 * m2;
    float n3 = clampn(v[4]); float t3 = tanhf(n3 / xn * at); mrow[1536 + j] = t3 / n3 * m3;
    if (j == 0) {
        g_tmu[r * 4 + 0] = t0; g_tmu[r * 4 + 1] = t1;
        g_tmu[r * 4 + 2] = t2; g_tmu[r * 4 + 3] = t3;
    }
}

// ---------------- per-step GEMM: z = [h|c] @ Wbig^T via tf32 tensor cores, split-K=8 ----------------
// grid (40, 8): 40 N-tiles (BN=64) x 8 K-chunks (64 wide). 128 threads = 4 warps; warp w owns M rows 16w..16w+15.
// mma.sync.aligned.m16n8k8.tf32: per k-step each warp loads 1 A frag + 8 B frags and issues 8 mma.
__global__ void __launch_bounds__(128) gemm_step() {
    __shared__ float As[64][76];   // stride 76: 16B-aligned rows, frag loads hit 32 distinct banks
    __shared__ float Bs[64][76];
    const int ct  = blockIdx.x;    // 0..39
    const int kc  = blockIdx.y;    // 0..7
    const int tid = threadIdx.x;
    const int col0 = ct * 64;
    const float* Aq = ((ct < 32) ? g_h : g_c) + kc * 64;
    const float* Bq = g_wbig + (size_t)col0 * 512 + kc * 64;

    // stage A (state, tf32-round here) and B (already tf32) tiles: 64 rows x 64 cols each
    #pragma unroll
    for (int i = 0; i < 8; i++) {
        int idx = tid + i * 128;          // 0..1023
        int r  = idx >> 4;                // 0..63
        int c4 = (idx & 15) << 2;         // 0,4,..,60
        float4 a = *(const float4*)(Aq + (size_t)r * 512 + c4);
        a.x = cvt_tf32(a.x); a.y = cvt_tf32(a.y); a.z = cvt_tf32(a.z); a.w = cvt_tf32(a.w);
        *(float4*)&As[r][c4] = a;
        *(float4*)&Bs[r][c4] = *(const float4*)(Bq + (size_t)r * 512 + c4);
    }
    __syncthreads();

    const int w    = tid >> 5;
    const int lane = tid & 31;
    const int gid  = lane >> 2;    // 0..7
    const int tig  = lane & 3;     // 0..3
    const int mrow = w * 16 + gid;

    float acc[8][4];
    #pragma unroll
    for (int nf = 0; nf < 8; nf++)
        #pragma unroll
        for (int p = 0; p < 4; p++) acc[nf][p] = 0.0f;

    #pragma unroll
    for (int ks = 0; ks < 8; ks++) {
        const int k0 = ks * 8;
        uint32_t a0 = __float_as_uint(As[mrow    ][k0 + tig    ]);
        uint32_t a1 = __float_as_uint(As[mrow + 8][k0 + tig    ]);
        uint32_t a2 = __float_as_uint(As[mrow    ][k0 + tig + 4]);
        uint32_t a3 = __float_as_uint(As[mrow + 8][k0 + tig + 4]);
        #pragma unroll
        for (int nf = 0; nf < 8; nf++) {
            uint32_t b0 = __float_as_uint(Bs[nf * 8 + gid][k0 + tig    ]);
            uint32_t b1 = __float_as_uint(Bs[nf * 8 + gid][k0 + tig + 4]);
            asm volatile(
                "mma.sync.aligned.m16n8k8.row.col.f32.tf32.tf32.f32 "
                "{%0,%1,%2,%3}, {%4,%5,%6,%7}, {%8,%9}, {%0,%1,%2,%3};"
                : "+f"(acc[nf][0]), "+f"(acc[nf][1]), "+f"(acc[nf][2]), "+f"(acc[nf][3])
                : "r"(a0), "r"(a1), "r"(a2), "r"(a3), "r"(b0), "r"(b1));
        }
    }

    float* Z = g_z + (size_t)kc * 64 * 2560 + col0;
    #pragma unroll
    for (int nf = 0; nf < 8; nf++) {
        const int cb = nf * 8 + tig * 2;
        *(float2*)&Z[(size_t)(mrow    ) * 2560 + cb] = make_float2(acc[nf][0], acc[nf][1]);
        *(float2*)&Z[(size_t)(mrow + 8) * 2560 + cb] = make_float2(acc[nf][2], acc[nf][3]);
    }
}

// ---------------- per-step elementwise: 8 reduction rounds ----------------
__global__ void __launch_bounds__(512) elem_step(int step, const float* __restrict__ ts, float* __restrict__ out) {
    const int b = blockIdx.x;
    const int j = threadIdx.x;
    const float t = ts[b * 128 + step];
    const float cj = g_c[b * 512 + j];
    const float hj = g_h[b * 512 + j];

    float zg[4] = {0.f, 0.f, 0.f, 0.f};
    float mcd = 0.f;
    #pragma unroll
    for (int s = 0; s < KSLICES; s++) {
        const float* zp = g_z + (size_t)s * 64 * 2560 + (size_t)b * 2560;
        #pragma unroll
        for (int g = 0; g < 4; g++) zg[g] += zp[g * 512 + j];
        mcd += zp[2048 + j];
    }
    const size_t row = (size_t)b * 128 + step;
    const float* mup = g_mu + row * 2048;
    float mug[4], tmu[4];
    #pragma unroll
    for (int g = 0; g < 4; g++) { mug[g] = mup[g * 512 + j]; tmu[g] = g_tmu[row * 4 + g]; }

    // R1: ||c||^2, ||h||^2, ||mcd||^2, ||z_g||^2 x4, <z_g,mu_g> x4  (11)
    float r1[11] = {cj * cj, hj * hj, mcd * mcd,
                    zg[0] * zg[0], zg[1] * zg[1], zg[2] * zg[2], zg[3] * zg[3],
                    zg[0] * mug[0], zg[1] * mug[1], zg[2] * mug[2], zg[3] * mug[3]};
    block_reduce_sum<11>(r1);
    const float c2 = r1[0];
    const float cn = clampn(c2), hn = clampn(r1[1]), mcdn = clampn(r1[2]);
    const float athn = artanhc(hn);
    const float alpha = tanhf(mcdn / cn * artanhc(cn)) / mcdn;   // M1 = alpha*mcd
    const float M1n = fmaxf(fabsf(alpha) * mcdn, MIN_NORM);
    const float gamma = artanhc(M1n) / M1n * alpha;              // T = tanh(gamma*mcd)
    const float T = tanhf(gamma * mcd);
    float sg[4];
    #pragma unroll
    for (int g = 0; g < 4; g++) {   // s_g = mobius_add(Wp_g, mu_g), Wp_g = (tgh/zn)*z_g
        float zn = clampn(r1[3 + g]);
        float tgh = tanhf(zn / hn * athn);
        float wc = tgh / zn;
        float x2 = tgh * tgh;
        float y2 = tmu[g] * tmu[g];
        float xy = wc * r1[7 + g];
        float den = fmaxf(1.f + 2.f * xy + x2 * y2, MIN_NORM);
        sg[g] = ((1.f + 2.f * xy + y2) * wc * zg[g] + (1.f - x2) * mug[g]) / den;
    }

    // R2: ||T||^2, ||s_g||^2 x4  (5)
    float r2[5] = {T * T, sg[0] * sg[0], sg[1] * sg[1], sg[2] * sg[2], sg[3] * sg[3]};
    block_reduce_sum<5>(r2);
    const float Tn = clampn(r2[0]);
    const float cs1n = tanhf(Tn);
    const float cs1 = cs1n / Tn * T;
    const float cs1_2 = cs1n * cs1n;
    float gate[4];
    #pragma unroll
    for (int g = 0; g < 4; g++) {
        float sn = clampn(r2[1 + g]);
        gate[g] = sigm(artanhc(sn) / sn * sg[g]);
    }
    const float gf = gate[0], gi = gate[1], go = gate[2], ctm = gate[3];
    out[row * 512 + j] = go;

    // R3: <cs1,c>, ||c_tmp||^2, ||i*c_tmp||^2  (3)
    const float ict = gi * ctm;
    float r3[3] = {cs1 * cj, ctm * ctm, ict * ict};
    block_reduce_sum<3>(r3);
    const float xy1 = -r3[0];
    const float ta = fabsf(t);
    const float xn_t  = fmaxf(ta * 22.62741699796952f, MIN_NORM);   // sqrt(512)
    const float wxn_t = fmaxf(ta * cs1n, MIN_NORM);
    const float cs2n = tanhf(wxn_t / xn_t * artanhc(xn_t));
    const float cs2 = cs2n / wxn_t * t * cs1;
    const float cs2sq = cs2n * cs2n;
    const float denl = fmaxf(1.f + 2.f * xy1 + cs1_2 * c2, MIN_NORM);
    const float cl = ((1.f + 2.f * xy1 + c2) * (-cs1) + (1.f - cs1_2) * cj) / denl;
    const float ctn = clampn(r3[1]), ictn = clampn(r3[2]);
    const float Pn = tanhf(ictn / ctn * artanhc(ctn));
    const float P = Pn / ictn * ict;
    const float P2s = Pn * Pn;

    // R4: ||cl||^2, <cl,cs2>  (2)
    float r4[2] = {cl * cl, cl * cs2};
    block_reduce_sum<2>(r4);
    const float cln2 = r4[0], xy5 = r4[1];
    const float den5 = fmaxf(1.f + 2.f * xy5 + cln2 * cs2sq, MIN_NORM);
    const float cadj = ((1.f + 2.f * xy5 + cs2sq) * cl + (1.f - cln2) * cs2) / den5;

    // R5: ||cadj||^2, ||f*cadj||^2  (2)
    const float fca = gf * cadj;
    float r5[2] = {cadj * cadj, fca * fca};
    block_reduce_sum<2>(r5);
    const float cadjn = clampn(r5[0]), fcan = clampn(r5[1]);
    const float Qn = tanhf(fcan / cadjn * artanhc(cadjn));
    const float Q = Qn / fcan * fca;
    const float Q2 = Qn * Qn;

    // R6: <P,Q>  (1)
    float r6[1] = {P * Q};
    block_reduce_sum<1>(r6);
    const float den7 = fmaxf(1.f + 2.f * r6[0] + P2s * Q2, MIN_NORM);
    const float cnew = ((1.f + 2.f * r6[0] + Q2) * P + (1.f - P2s) * Q) / den7;

    // R7: ||u||^2, u = tanh(cnew)  (1)
    const float u = tanhf(cnew);
    float r7[1] = {u * u};
    block_reduce_sum<1>(r7);
    const float un = clampn(r7[0]);
    const float en_exact = tanhf(un);
    const float e = en_exact / un * u;
    const float en = fmaxf(en_exact, MIN_NORM);

    // R8: ||o*e||^2  (1)
    const float oe = go * e;
    float r8[1] = {oe * oe};
    block_reduce_sum<1>(r8);
    const float oen = clampn(r8[0]);
    const float hnew = tanhf(oen / en * artanhc(en)) / oen * oe;

    g_h[b * 512 + j] = hnew;
    g_c[b * 512 + j] = cnew;
    if (step == 127) {
        out[(size_t)64 * 128 * 512 + (size_t)b * 512 + j] = hnew;
        out[(size_t)64 * 128 * 512 + (size_t)64 * 512 + (size_t)b * 512 + j] = cnew;
    }
}

// ---------------- launch ----------------
extern "C" void kernel_launch(void* const* d_in, const int* in_sizes, int n_in,
                              void* d_out, int out_size) {
    const float* inputs = (const float*)d_in[0];
    const float* ts     = (const float*)d_in[1];
    const float* h0     = (const float*)d_in[2];
    const float* c0     = (const float*)d_in[3];
    const float* Wall   = (const float*)d_in[4];
    const float* Uall   = (const float*)d_in[5];
    const float* Wd     = (const float*)d_in[6];
    float* out = (float*)d_out;

    cudaMemcpyToSymbolAsync(g_h, h0, 64 * 512 * sizeof(float), 0, cudaMemcpyDeviceToDevice, 0);
    cudaMemcpyToSymbolAsync(g_c, c0, 64 * 512 * sizeof(float), 0, cudaMemcpyDeviceToDevice, 0);

    prep_w<<<(2560 * 512 + 255) / 256, 256>>>(Wall, Wd);
    gemm_pre<<<dim3(16, 64), 256>>>(inputs, Uall);
    scale_mu<<<8192, 512>>>(inputs);

    for (int t = 0; t < 128; t++) {
        gemm_step<<<dim3(40, 8), 128>>>();
        elem_step<<<64, 512>>>(t, ts, out);
    }
}